// round 8
// baseline (speedup 1.0000x reference)
#include <cuda_runtime.h>
#include <mma.h>
#include <cstdint>
#include <math.h>

#define BB 64
#define SS 96
#define HH 1024
#define EE 512
#define VV 32000
#define TT 32
#define G3 3072
#define NT 64                 // logits N tile per CTA
#define KC 32                 // K chunk (floats)
#define NBLK 500              // VV / NT
#define LDS 36                // smem leading dim (floats)

using namespace nvcuda;

// ---------------- device scratch ----------------
__device__ float g_u[HH];
__device__ float g_ctx[BB * HH];
__device__ float g_gictx[BB * G3];
__device__ float g_giacc[BB * G3];
__device__ float g_ghacc[BB * G3];
__device__ float g_h[2][BB * HH];
__device__ int   g_tok[BB];
__device__ float g_pv[BB * NBLK];
__device__ int   g_pi[BB * NBLK];

// ---------------- helpers ----------------
union F2U { float2 f; unsigned long long u; };
__device__ __forceinline__ float2 ffma2(float2 a, float2 b, float2 c) {
    F2U A, B, C, D;
    A.f = a; B.f = b; C.f = c;
    asm("fma.rn.f32x2 %0, %1, %2, %3;" : "=l"(D.u) : "l"(A.u), "l"(B.u), "l"(C.u));
    return D.f;
}
__device__ __forceinline__ float to_tf32(float v) {
    float r;
    asm("cvt.rna.tf32.f32 %0, %1;" : "=f"(r) : "f"(v));
    return r;
}

// ---------------- init (R2 exact) ----------------
__global__ void k_init(const float* __restrict__ eh) {
    int i = blockIdx.x * blockDim.x + threadIdx.x;
    if (i < BB * HH) g_h[0][i] = eh[i];
    if (i < BB)      g_tok[i] = 1;
}

// ---------------- u = Ua^T Va (R2 exact) ----------------
__global__ void __launch_bounds__(256) k_u(const float* __restrict__ Ua,
                                           const float* __restrict__ Va) {
    __shared__ float sva[HH];
    for (int i = threadIdx.x; i < HH; i += 256) sva[i] = Va[i];
    __syncthreads();
    int h = blockIdx.x * 256 + threadIdx.x;
    float acc = 0.f;
    for (int g = 0; g < HH; ++g) acc = fmaf(sva[g], Ua[(size_t)g * HH + h], acc);
    g_u[h] = acc;
}

// ---------------- attention (R2 exact) ----------------
__global__ void __launch_bounds__(128) k_attn(const float* __restrict__ keys,
                                              float* __restrict__ out_attn) {
    __shared__ float s_w[SS];
    __shared__ float s_u[HH];
    int b = blockIdx.x, tid = threadIdx.x;
    for (int i = tid; i < HH; i += 128) s_u[i] = g_u[i];
    __syncthreads();
    int warp = tid >> 5, lane = tid & 31;
    const float* kb = keys + (size_t)b * SS * HH;
    for (int s = warp; s < SS; s += 4) {
        const float* kr = kb + (size_t)s * HH;
        float acc = 0.f;
        for (int k = lane; k < HH; k += 32) acc = fmaf(kr[k], s_u[k], acc);
        #pragma unroll
        for (int o = 16; o; o >>= 1) acc += __shfl_down_sync(0xffffffffu, acc, o);
        if (!lane) s_w[s] = acc;
    }
    __syncthreads();
    if (warp == 0) {
        float m = -1e30f;
        for (int s = lane; s < SS; s += 32) m = fmaxf(m, s_w[s]);
        #pragma unroll
        for (int o = 16; o; o >>= 1) m = fmaxf(m, __shfl_xor_sync(0xffffffffu, m, o));
        float sum = 0.f;
        for (int s = lane; s < SS; s += 32) { float e = expf(s_w[s] - m); s_w[s] = e; sum += e; }
        #pragma unroll
        for (int o = 16; o; o >>= 1) sum += __shfl_xor_sync(0xffffffffu, sum, o);
        float inv = 1.f / sum;
        for (int s = lane; s < SS; s += 32) s_w[s] *= inv;
    }
    __syncthreads();
    for (int h = tid; h < HH; h += 128) {
        float acc = 0.f;
        for (int s = 0; s < SS; ++s) acc = fmaf(s_w[s], kb[(size_t)s * HH + h], acc);
        g_ctx[b * HH + h] = acc;
    }
    float* oa = out_attn + (size_t)b * TT * SS;
    for (int e = tid; e < TT * SS; e += 128) oa[e] = s_w[e % SS];
}

// ---------------- fp32 64x32 GEMM tile (R2 exact) ----------------
#define KT 32
__device__ __forceinline__ void gemm64x32(
    const float* __restrict__ Aptr, const float* __restrict__ emb_table,
    const float* __restrict__ W, int ldw, int woff,
    int j0, int K, float* __restrict__ C)
{
    __shared__ float As[KT][68];
    __shared__ float Ws[KT][36];
    __shared__ int stok[BB];
    const int tid = threadIdx.x;  // 128 threads
    if (Aptr == nullptr && tid < BB) stok[tid] = g_tok[tid];
    __syncthreads();

    const int rthr = tid & 15, bthr = tid >> 4;
    const int r0 = rthr * 2, b0 = bthr * 8;
    float2 acc[2][4] = {};

    for (int k0 = 0; k0 < K; k0 += KT) {
        #pragma unroll
        for (int r = 0; r < 4; ++r) {
            int idx = r * 128 + tid;
            int bb = idx & 63, k4 = (idx >> 6) * 4;
            float4 v;
            if (Aptr) v = *(const float4*)(Aptr + (size_t)bb * K + k0 + k4);
            else {
                v = *(const float4*)(emb_table + (size_t)stok[bb] * EE + k0 + k4);
                v.x = fmaxf(v.x, 0.f); v.y = fmaxf(v.y, 0.f);
                v.z = fmaxf(v.z, 0.f); v.w = fmaxf(v.w, 0.f);
            }
            As[k4 + 0][bb] = v.x; As[k4 + 1][bb] = v.y;
            As[k4 + 2][bb] = v.z; As[k4 + 3][bb] = v.w;
        }
        #pragma unroll
        for (int r = 0; r < 2; ++r) {
            int idx = r * 128 + tid;
            int rr = idx & 31, k4 = (idx >> 5) * 4;
            float4 v = *(const float4*)(W + (size_t)(j0 + rr) * ldw + woff + k0 + k4);
            Ws[k4 + 0][rr] = v.x; Ws[k4 + 1][rr] = v.y;
            Ws[k4 + 2][rr] = v.z; Ws[k4 + 3][rr] = v.w;
        }
        __syncthreads();
        #pragma unroll
        for (int k = 0; k < KT; ++k) {
            float2 wv = *(const float2*)&Ws[k][r0];
            float2 w0 = make_float2(wv.x, wv.x);
            float2 w1 = make_float2(wv.y, wv.y);
            float4 a0 = *(const float4*)&As[k][b0];
            float4 a1 = *(const float4*)&As[k][b0 + 4];
            float2 ap[4] = { {a0.x,a0.y},{a0.z,a0.w},{a1.x,a1.y},{a1.z,a1.w} };
            #pragma unroll
            for (int p = 0; p < 4; ++p) {
                acc[0][p] = ffma2(ap[p], w0, acc[0][p]);
                acc[1][p] = ffma2(ap[p], w1, acc[1][p]);
            }
        }
        __syncthreads();
    }
    #pragma unroll
    for (int ri = 0; ri < 2; ++ri)
        #pragma unroll
        for (int p = 0; p < 4; ++p) {
            int j = j0 + r0 + ri;
            C[(b0 + 2 * p)     * G3 + j] = acc[ri][p].x;
            C[(b0 + 2 * p + 1) * G3 + j] = acc[ri][p].y;
        }
}

__global__ void __launch_bounds__(128) k_gictx(const float* __restrict__ W_ih) {
    gemm64x32(g_ctx, nullptr, W_ih, EE + HH, EE, blockIdx.x * 32, HH, g_gictx);
}
__global__ void __launch_bounds__(128) k_pregates(int cur,
        const float* __restrict__ W_ih, const float* __restrict__ W_hh,
        const float* __restrict__ emb_table) {
    int bx = blockIdx.x;
    if (bx < 96) gemm64x32(nullptr, emb_table, W_ih, EE + HH, 0, bx * 32, EE, g_giacc);
    else         gemm64x32(g_h[cur], nullptr,  W_hh, HH,      0, (bx - 96) * 32, HH, g_ghacc);
}

// ---------------- GRU gates (R2 exact) ----------------
__global__ void __launch_bounds__(256) k_gates(int cur,
        const float* __restrict__ b_ih, const float* __restrict__ b_hh,
        float* __restrict__ out_h) {
    int idx = blockIdx.x * 256 + threadIdx.x;
    int b = idx >> 10, i = idx & 1023;
    int base = b * G3;
    float gir = g_giacc[base + i]        + g_gictx[base + i]        + b_ih[i];
    float giz = g_giacc[base + 1024 + i] + g_gictx[base + 1024 + i] + b_ih[1024 + i];
    float gin = g_giacc[base + 2048 + i] + g_gictx[base + 2048 + i] + b_ih[2048 + i];
    float ghr = g_ghacc[base + i]        + b_hh[i];
    float ghz = g_ghacc[base + 1024 + i] + b_hh[1024 + i];
    float ghn = g_ghacc[base + 2048 + i] + b_hh[2048 + i];
    float r = 1.f / (1.f + expf(-(gir + ghr)));
    float z = 1.f / (1.f + expf(-(giz + ghz)));
    float n = tanhf(gin + r * ghn);
    float h = g_h[cur][idx];
    float hn = (1.f - z) * n + z * h;
    g_h[cur ^ 1][idx] = hn;
    if (out_h) out_h[idx] = hn;
}

// ============ split-TF32 logits GEMM: out[64,64] = h @ W_out^T + b ============
// 3xTF32: v = hi + lo (both tf32-valued floats). acc += aHi*wHi + aHi*wLo + aLo*wHi.
// All three passes accumulate into ONE fp32 accumulator — no scaling, no combine.
__global__ void __launch_bounds__(256) k_mm_logits(int hsel,
        const float* __restrict__ W_out, const float* __restrict__ bias,
        float* __restrict__ outL, int t) {
    __shared__ float smem[4 * 64 * LDS];   // 36864 B
    float* sAhi = smem;
    float* sAlo = smem + 64 * LDS;
    float* sWhi = smem + 2 * 64 * LDS;
    float* sWlo = smem + 3 * 64 * LDS;

    const int tid = threadIdx.x;           // 256 threads, 8 warps
    const int wid = tid >> 5;
    const int wm = wid & 3, wn = wid >> 2; // 4x2 warp grid over 64x64
    const int n0 = blockIdx.x * NT;
    const float* __restrict__ hsrc = g_h[hsel];

    wmma::fragment<wmma::accumulator, 16, 16, 8, float> acc[2];
    wmma::fill_fragment(acc[0], 0.f);
    wmma::fill_fragment(acc[1], 0.f);

    for (int k0 = 0; k0 < HH; k0 += KC) {
        // A tile: 64 rows x 32 floats (2 float4 per thread)
        #pragma unroll
        for (int i = tid; i < 512; i += 256) {
            int r = i >> 3, c4 = (i & 7) * 4;
            float4 v = *(const float4*)(hsrc + (size_t)r * HH + k0 + c4);
            float4 hi, lo;
            hi.x = to_tf32(v.x); lo.x = to_tf32(v.x - hi.x);
            hi.y = to_tf32(v.y); lo.y = to_tf32(v.y - hi.y);
            hi.z = to_tf32(v.z); lo.z = to_tf32(v.z - hi.z);
            hi.w = to_tf32(v.w); lo.w = to_tf32(v.w - hi.w);
            *(float4*)(sAhi + r * LDS + c4) = hi;
            *(float4*)(sAlo + r * LDS + c4) = lo;
        }
        // W tile: 64 rows x 32 floats
        #pragma unroll
        for (int i = tid; i < 512; i += 256) {
            int r = i >> 3, c4 = (i & 7) * 4;
            float4 v = *(const float4*)(W_out + (size_t)(n0 + r) * HH + k0 + c4);
            float4 hi, lo;
            hi.x = to_tf32(v.x); lo.x = to_tf32(v.x - hi.x);
            hi.y = to_tf32(v.y); lo.y = to_tf32(v.y - hi.y);
            hi.z = to_tf32(v.z); lo.z = to_tf32(v.z - hi.z);
            hi.w = to_tf32(v.w); lo.w = to_tf32(v.w - hi.w);
            *(float4*)(sWhi + r * LDS + c4) = hi;
            *(float4*)(sWlo + r * LDS + c4) = lo;
        }
        __syncthreads();

        #pragma unroll
        for (int kk = 0; kk < KC / 8; ++kk) {
            wmma::fragment<wmma::matrix_a, 16, 16, 8, wmma::precision::tf32, wmma::row_major> faH, faL;
            wmma::load_matrix_sync(faH, sAhi + (wm * 16) * LDS + kk * 8, LDS);
            wmma::load_matrix_sync(faL, sAlo + (wm * 16) * LDS + kk * 8, LDS);
            #pragma unroll
            for (int nt = 0; nt < 2; ++nt) {
                int nc = wn * 32 + nt * 16;
                wmma::fragment<wmma::matrix_b, 16, 16, 8, wmma::precision::tf32, wmma::col_major> fbH, fbL;
                wmma::load_matrix_sync(fbH, sWhi + nc * LDS + kk * 8, LDS);
                wmma::load_matrix_sync(fbL, sWlo + nc * LDS + kk * 8, LDS);
                wmma::mma_sync(acc[nt], faH, fbH, acc[nt]);
                wmma::mma_sync(acc[nt], faH, fbL, acc[nt]);
                wmma::mma_sync(acc[nt], faL, fbH, acc[nt]);
            }
        }
        __syncthreads();
    }

    // epilogue: dump accumulators, add bias, store, per-row argmax partial
    float* sbuf = smem;    // [64][64]
    wmma::store_matrix_sync(sbuf + (wm * 16) * NT + wn * 32,      acc[0], NT, wmma::mem_row_major);
    wmma::store_matrix_sync(sbuf + (wm * 16) * NT + wn * 32 + 16, acc[1], NT, wmma::mem_row_major);
    __syncthreads();

    if (tid < 64) {
        int b = tid;
        float* out = outL + (size_t)b * TT * VV + (size_t)t * VV + n0;
        float bestv = -1e30f; int besti = 0;
        #pragma unroll
        for (int n = 0; n < NT; n += 4) {
            float4 v = *(float4*)&sbuf[b * NT + n];
            float4 bi = *(const float4*)&bias[n0 + n];
            v.x += bi.x; v.y += bi.y; v.z += bi.z; v.w += bi.w;
            *(float4*)(out + n) = v;
            if (v.x > bestv) { bestv = v.x; besti = n0 + n; }
            if (v.y > bestv) { bestv = v.y; besti = n0 + n + 1; }
            if (v.z > bestv) { bestv = v.z; besti = n0 + n + 2; }
            if (v.w > bestv) { bestv = v.w; besti = n0 + n + 3; }
        }
        g_pv[b * NBLK + blockIdx.x] = bestv;
        g_pi[b * NBLK + blockIdx.x] = besti;
    }
}

// ---------------- argmax finalize ----------------
__global__ void __launch_bounds__(256) k_amax_fin() {
    int b = blockIdx.x, tid = threadIdx.x;
    float v = -1e30f; int i = 0x7fffffff;
    for (int p = tid; p < NBLK; p += 256) {
        float pv = g_pv[b * NBLK + p]; int pi = g_pi[b * NBLK + p];
        if (pv > v || (pv == v && pi < i)) { v = pv; i = pi; }
    }
    __shared__ float sv[256]; __shared__ int si[256];
    sv[tid] = v; si[tid] = i; __syncthreads();
    for (int s = 128; s; s >>= 1) {
        if (tid < s && (sv[tid + s] > sv[tid] ||
                        (sv[tid + s] == sv[tid] && si[tid + s] < si[tid]))) {
            sv[tid] = sv[tid + s]; si[tid] = si[tid + s];
        }
        __syncthreads();
    }
    if (!tid) g_tok[b] = si[0];
}

// ---------------- host ----------------
extern "C" void kernel_launch(void* const* d_in, const int* in_sizes, int n_in,
                              void* d_out, int out_size) {
    const float* enc   = (const float*)d_in[0];
    const float* eh    = (const float*)d_in[1];
    const float* embt  = (const float*)d_in[2];
    // d_in[3] = Wa: dead code (softmax shift invariance)
    const float* Ua    = (const float*)d_in[4];
    const float* Va    = (const float*)d_in[5];
    const float* W_ih  = (const float*)d_in[6];
    const float* W_hh  = (const float*)d_in[7];
    const float* b_ih  = (const float*)d_in[8];
    const float* b_hh  = (const float*)d_in[9];
    const float* W_out = (const float*)d_in[10];
    const float* b_out = (const float*)d_in[11];

    float* outL = (float*)d_out;
    float* outH = outL + (size_t)BB * TT * VV;
    float* outA = outH + (size_t)BB * HH;

    k_init<<<(BB * HH + 255) / 256, 256>>>(eh);
    k_u<<<HH / 256, 256>>>(Ua, Va);
    k_attn<<<BB, 128>>>(enc, outA);
    k_gictx<<<96, 128>>>(W_ih);

    for (int t = 0; t < TT; ++t) {
        int cur = t & 1;
        k_pregates<<<192, 128>>>(cur, W_ih, W_hh, embt);
        k_gates<<<BB * HH / 256, 256>>>(cur, b_ih, b_hh, (t == TT - 1) ? outH : nullptr);
        k_mm_logits<<<NBLK, 256>>>(cur ^ 1, W_out, b_out, outL, t);
        if (t < TT - 1) k_amax_fin<<<BB, 256>>>();
    }
}